// round 1
// baseline (speedup 1.0000x reference)
#include <cuda_runtime.h>
#include <math.h>

#define NN 20000
#define NE 320000
#define C  64
#define NG 32
#define NL 8

// ---------------- scratch (device globals; no allocation allowed) ----------
__device__ float g_h [NN*C];
__device__ float g_xl[NN*C];
__device__ float g_xr[NN*C];
__device__ float g_g [NN*C];
__device__ int   g_rowptr[NN+1];
__device__ int   g_cursor[NN];
__device__ int   g_col[NE];
__device__ float g_bnsum[C];
__device__ float g_bnsq [C];
__device__ float g_pool[2*NG*C];
__device__ float g_pcnt[2*NG];

// ---------------- CSR build ------------------------------------------------
__global__ void k_zero_cnt(){
    int i = blockIdx.x*blockDim.x + threadIdx.x;
    if (i < NN) g_cursor[i] = 0;
}

__global__ void k_zero_pool(){
    int i = blockIdx.x*blockDim.x + threadIdx.x;
    if (i < 2*NG*C) g_pool[i] = 0.f;
    if (i < 2*NG)   g_pcnt[i] = 0.f;
}

__global__ void k_hist(const int* __restrict__ ei){
    int e = blockIdx.x*blockDim.x + threadIdx.x;
    if (e < NE) atomicAdd(&g_cursor[ei[NE + e]], 1);
}

// single-block exclusive scan over 20000 counts -> rowptr, cursor
__global__ void k_scan(){
    __shared__ int part[1024];
    int tid = threadIdx.x;
    const int CH = (NN + 1023)/1024;   // 20
    int base = tid*CH;
    int s = 0;
    for (int i=0;i<CH;i++){ int idx=base+i; if (idx<NN) s += g_cursor[idx]; }
    part[tid] = s;
    __syncthreads();
    for (int off=1; off<1024; off<<=1){
        int v = (tid>=off) ? part[tid-off] : 0;
        __syncthreads();
        part[tid] += v;
        __syncthreads();
    }
    int run = (tid==0) ? 0 : part[tid-1];
    for (int i=0;i<CH;i++){
        int idx = base+i;
        if (idx<NN){
            int cnt = g_cursor[idx];
            g_rowptr[idx] = run;
            g_cursor[idx] = run;     // scatter cursor
            run += cnt;
        }
    }
    if (tid == 1023) g_rowptr[NN] = run;  // = NE
}

__global__ void k_scatter(const int* __restrict__ ei){
    int e = blockIdx.x*blockDim.x + threadIdx.x;
    if (e < NE){
        int d = ei[NE+e], s = ei[e];
        int p = atomicAdd(&g_cursor[d], 1);
        g_col[p] = s;
    }
}

// ---------------- node_lin: h = x @ Wn + bnode -----------------------------
__global__ void k_nodelin(const float* __restrict__ x, const float* __restrict__ Wn,
                          const float* __restrict__ bn){
    int i = blockIdx.x*blockDim.x + threadIdx.x;
    if (i >= NN*C) return;
    int n = i>>6, o = i&63;
    float a = bn[o];
    #pragma unroll
    for (int k=0;k<5;k++) a = fmaf(x[n*5+k], Wn[k*C+o], a);
    g_h[i] = a;
}

// ---------------- per-layer GEMMs: xl = h@Wl+bl, xr = h@Wr+br --------------
__global__ void __launch_bounds__(256) k_gemm(
        const float* __restrict__ Wl, const float* __restrict__ bl,
        const float* __restrict__ Wr, const float* __restrict__ br){
    __shared__ float wls[C*C], wrs[C*C], hs[64*C];
    int tid = threadIdx.x;
    if (blockIdx.x == 0 && tid < 2*C){      // zero BN accumulators for the layer
        if (tid < C) g_bnsum[tid] = 0.f; else g_bnsq[tid-C] = 0.f;
    }
    int n0 = blockIdx.x * 64;
    for (int i=tid;i<C*C;i+=256){ wls[i]=Wl[i]; wrs[i]=Wr[i]; }
    for (int i=tid;i<64*C;i+=256){
        int gidx = n0*C + i;
        hs[i] = (gidx < NN*C) ? g_h[gidx] : 0.f;
    }
    __syncthreads();
    int col = tid & 63, grp = tid >> 6;     // 4 groups x 16 nodes
    float accl[16], accr[16];
    float b0 = bl[col], b1 = br[col];
    #pragma unroll
    for (int j=0;j<16;j++){ accl[j]=b0; accr[j]=b1; }
    for (int k=0;k<C;k++){
        float wl = wls[k*C+col], wr = wrs[k*C+col];
        #pragma unroll
        for (int j=0;j<16;j++){
            float hv = hs[(grp*16+j)*C + k];
            accl[j] = fmaf(hv, wl, accl[j]);
            accr[j] = fmaf(hv, wr, accr[j]);
        }
    }
    #pragma unroll
    for (int j=0;j<16;j++){
        int n = n0 + grp*16 + j;
        if (n < NN){ g_xl[n*C+col] = accl[j]; g_xr[n*C+col] = accr[j]; }
    }
}

// ---------------- edge aggregation: online softmax, CSR by dst -------------
// 64 threads per node (thread = feature t; head = t>>4). Self-loop handled
// explicitly (j = beg-1). Fused BN partial sums.
__global__ void __launch_bounds__(256) k_edge(const float* __restrict__ att,
                                              const float* __restrict__ cb){
    __shared__ float bsum[C], bsq[C];
    int tid = threadIdx.x;
    if (tid < C){ bsum[tid]=0.f; bsq[tid]=0.f; }
    __syncthreads();

    int n = blockIdx.x*4 + (tid>>6);   // grid = NN/4 exactly
    int t = tid & 63;
    float xrv = g_xr[n*C+t];
    float av  = att[t];
    float m = -3.4e38f, s = 0.f, o = 0.f;
    int beg = g_rowptr[n], end = g_rowptr[n+1];
    for (int j = beg-1; j < end; j++){
        int src = (j < beg) ? n : g_col[j];
        float xlv = g_xl[src*C+t];
        float e = xlv + xrv;
        e = (e > 0.f) ? e : 0.2f*e;                   // leaky_relu(0.2)
        float p = e * av;
        p += __shfl_xor_sync(0xffffffffu, p, 8, 16);  // per-head (16-lane) dot
        p += __shfl_xor_sync(0xffffffffu, p, 4, 16);
        p += __shfl_xor_sync(0xffffffffu, p, 2, 16);
        p += __shfl_xor_sync(0xffffffffu, p, 1, 16);
        float nm = fmaxf(m, p);
        float sc = __expf(m - nm);
        float w  = __expf(p - nm);
        s = s*sc + w;
        o = fmaf(w, xlv, o*sc);
        m = nm;
    }
    float gv = o/s + cb[t];
    g_g[n*C+t] = gv;
    atomicAdd(&bsum[t], gv);
    atomicAdd(&bsq[t],  gv*gv);
    __syncthreads();
    if (tid < C){
        atomicAdd(&g_bnsum[tid], bsum[tid]);
        atomicAdd(&g_bnsq [tid], bsq[tid]);
    }
}

// ---------------- batchnorm + elu + residual -------------------------------
__global__ void k_update(const float* __restrict__ gamma, const float* __restrict__ beta){
    int i = blockIdx.x*blockDim.x + threadIdx.x;
    if (i >= NN*C) return;
    int o = i & 63;
    float mu  = g_bnsum[o] * (1.f/NN);
    float var = g_bnsq[o] * (1.f/NN) - mu*mu;
    float gh = (g_g[i]-mu) * rsqrtf(var + 1e-5f) * gamma[o] + beta[o];
    float el = (gh > 0.f) ? gh : (__expf(gh)-1.f);    // elu
    g_h[i] += el;
}

// ---------------- global mean pool -----------------------------------------
__global__ void k_pool(const int* __restrict__ batch, int half){
    int i = blockIdx.x*blockDim.x + threadIdx.x;
    if (i >= NN*C) return;
    int n = i>>6, o = i&63;
    int b = batch[n];
    atomicAdd(&g_pool[half*NG*C + b*C + o], g_h[i]);
    if (o == 0) atomicAdd(&g_pcnt[half*NG + b], 1.f);
}

// ---------------- head MLP (tiny) ------------------------------------------
__global__ void __launch_bounds__(256) k_head(
        const float* __restrict__ f1w, const float* __restrict__ f1b,
        const float* __restrict__ f2w, const float* __restrict__ f2b,
        const float* __restrict__ f3w, const float* __restrict__ f3b,
        float* __restrict__ out){
    __shared__ float cvec[128], h1[256], h2[128];
    int b = blockIdx.x, tid = threadIdx.x;
    if (tid < 64)
        cvec[tid] = g_pool[b*C+tid] / fmaxf(g_pcnt[b], 1.f);
    else if (tid < 128)
        cvec[tid] = g_pool[NG*C + b*C + (tid-64)] / fmaxf(g_pcnt[NG+b], 1.f);
    __syncthreads();
    float a = f1b[tid];
    for (int k=0;k<128;k++) a = fmaf(cvec[k], f1w[k*256+tid], a);
    h1[tid] = fmaxf(a, 0.f);
    __syncthreads();
    if (tid < 128){
        float a2 = f2b[tid];
        for (int k=0;k<256;k++) a2 = fmaf(h1[k], f2w[k*128+tid], a2);
        h2[tid] = fmaxf(a2, 0.f);
    }
    __syncthreads();
    if (tid == 0){
        float a3 = f3b[0];
        for (int k=0;k<128;k++) a3 = fmaf(h2[k], f3w[k], a3);
        out[b] = a3;
    }
}

// ---------------- launch ----------------------------------------------------
extern "C" void kernel_launch(void* const* d_in, const int* in_sizes, int n_in,
                              void* d_out, int out_size){
    const float *x[2]; const int *ei[2]; const int *bt[2];
    // robust to metadata ordering: reference-signature order has
    // in_sizes[1] = 2*NE (edge_index1); setup-dict order has in_sizes[1]=NN*5 (x2)
    if (in_sizes[1] == 2*NE){
        x[0]=(const float*)d_in[0]; ei[0]=(const int*)d_in[1]; bt[0]=(const int*)d_in[2];
        x[1]=(const float*)d_in[3]; ei[1]=(const int*)d_in[4]; bt[1]=(const int*)d_in[5];
    } else {
        x[0]=(const float*)d_in[0]; x[1]=(const float*)d_in[1];
        ei[0]=(const int*)d_in[2]; ei[1]=(const int*)d_in[3];
        bt[0]=(const int*)d_in[4]; bt[1]=(const int*)d_in[5];
    }
    const float* Wn    =(const float*)d_in[6];
    const float* bnode =(const float*)d_in[7];
    const float* Wl    =(const float*)d_in[8];
    const float* bl    =(const float*)d_in[9];
    const float* Wr    =(const float*)d_in[10];
    const float* br    =(const float*)d_in[11];
    const float* att   =(const float*)d_in[12];
    const float* cbias =(const float*)d_in[13];
    const float* gamma =(const float*)d_in[14];
    const float* beta  =(const float*)d_in[15];
    const float* f1w   =(const float*)d_in[16];
    const float* f1b   =(const float*)d_in[17];
    const float* f2w   =(const float*)d_in[18];
    const float* f2b   =(const float*)d_in[19];
    const float* f3w   =(const float*)d_in[20];
    const float* f3b   =(const float*)d_in[21];

    k_zero_pool<<<(2*NG*C+255)/256, 256>>>();
    for (int g=0; g<2; g++){
        k_zero_cnt<<<(NN+255)/256,256>>>();
        k_hist   <<<NE/256,256>>>(ei[g]);
        k_scan   <<<1,1024>>>();
        k_scatter<<<NE/256,256>>>(ei[g]);
        k_nodelin<<<NN*C/256,256>>>(x[g], Wn, bnode);
        for (int l=0;l<NL;l++){
            k_gemm  <<<(NN+63)/64,256>>>(Wl+l*C*C, bl+l*C, Wr+l*C*C, br+l*C);
            k_edge  <<<NN/4,256>>>(att+l*C, cbias+l*C);
            k_update<<<NN*C/256,256>>>(gamma+l*C, beta+l*C);
        }
        k_pool<<<NN*C/256,256>>>(bt[g], g);
    }
    k_head<<<NG,256>>>(f1w,f1b,f2w,f2b,f3w,f3b,(float*)d_out);
}

// round 4
// speedup vs baseline: 1.1986x; 1.1986x over previous
#include <cuda_runtime.h>
#include <math.h>

#define NN 20000
#define NE 320000
#define C  64
#define NG 32
#define NL 8
#define TN 128          // gemm node tile

// ---------------- scratch (device globals; no allocation allowed) ----------
__device__ float4 g_xl4[NN*16];
__device__ float4 g_xr4[NN*16];
__device__ float4 g_g4 [NN*16];
__device__ float  g_h  [NN*C];
__device__ int    g_rowptr[NN+1];
__device__ int    g_cursor[NN];
__device__ int    g_col[NE];
__device__ int    g_blks[32];
__device__ float  g_bnsum[2][C];
__device__ float  g_bnsq [2][C];
__device__ float  g_pool[2*NG*C];
__device__ float  g_pcnt[2*NG];

// ---------------- CSR build -----------------------------------------------
__global__ void k_zero_cnt(){
    int i = blockIdx.x*blockDim.x + threadIdx.x;
    if (i < NN) g_cursor[i] = 0;
}
__global__ void k_zero_pool(){
    int i = blockIdx.x*blockDim.x + threadIdx.x;
    if (i < 2*NG*C) g_pool[i] = 0.f;
    if (i < 2*NG)   g_pcnt[i] = 0.f;
}
__global__ void k_hist(const int* __restrict__ ei){
    int e = blockIdx.x*blockDim.x + threadIdx.x;
    if (e < NE) atomicAdd(&g_cursor[ei[NE + e]], 1);
}
// phase 1: 20 blocks x 1024, block-local exclusive scan
__global__ void __launch_bounds__(1024) k_scan1(){
    __shared__ int s[1024];
    int tid = threadIdx.x;
    int gid = blockIdx.x*1024 + tid;
    int v = (gid < NN) ? g_cursor[gid] : 0;
    s[tid] = v; __syncthreads();
    for (int off=1; off<1024; off<<=1){
        int t = (tid>=off) ? s[tid-off] : 0;
        __syncthreads();
        s[tid] += t;
        __syncthreads();
    }
    if (gid < NN) g_rowptr[gid] = s[tid] - v;     // exclusive within block
    if (tid == 1023) g_blks[blockIdx.x] = s[1023];
}
// phase 2: serial scan of 20 block sums
__global__ void k_scan2(){
    if (threadIdx.x == 0){
        int r = 0;
        for (int i=0;i<20;i++){ int c = g_blks[i]; g_blks[i] = r; r += c; }
        g_rowptr[NN] = r;
    }
}
// phase 3: add block offsets, init cursor
__global__ void __launch_bounds__(1024) k_scan3(){
    int gid = blockIdx.x*1024 + threadIdx.x;
    if (gid < NN){
        int v = g_rowptr[gid] + g_blks[blockIdx.x];
        g_rowptr[gid] = v;
        g_cursor[gid] = v;
    }
}
__global__ void k_scatter(const int* __restrict__ ei){
    int e = blockIdx.x*blockDim.x + threadIdx.x;
    if (e < NE){
        int d = ei[NE+e], s = ei[e];
        int p = atomicAdd(&g_cursor[d], 1);
        g_col[p] = s;
    }
}

// ---------------- fused update + dual GEMM ---------------------------------
__global__ void __launch_bounds__(256,2) k_gemm(
        const float* __restrict__ Wl, const float* __restrict__ bl,
        const float* __restrict__ Wr, const float* __restrict__ br,
        const float* __restrict__ gamma, const float* __restrict__ beta,
        int layer,
        const float* __restrict__ x, const float* __restrict__ Wn,
        const float* __restrict__ bnode)
{
    extern __shared__ float sm[];
    float* ws  = sm;                 // 64*128
    float* hs  = sm + 8192;          // 128*65 (padded)
    float* bc  = hs + TN*65;         // 128
    float* mus = bc + 128;           // 64
    float* rss = mus + 64;           // 64
    __shared__ float wn[320];
    __shared__ float xs[TN*5];

    int tid = threadIdx.x;
    int n0  = blockIdx.x * TN;
    const float* g_hf = g_h;
    const float* g_gf = (const float*)g_g4;

    for (int i=tid;i<8192;i+=256){
        int k=i>>7, c=i&127;
        ws[i] = (c<64) ? Wl[k*64+c] : Wr[k*64+(c-64)];
    }
    if (tid < 128) bc[tid] = (tid<64) ? bl[tid] : br[tid-64];
    if (blockIdx.x == 0 && tid >= 128 && tid < 256){   // zero this layer's BN buffer
        int nb = layer & 1, t = tid - 128;
        if (t < 64) g_bnsum[nb][t] = 0.f; else g_bnsq[nb][t-64] = 0.f;
    }

    if (layer == 0){
        for (int i=tid;i<320;i+=256) wn[i] = Wn[i];   // FIX: was `if (tid<320)` with 256 threads
        for (int i=tid;i<TN*5;i+=256){
            int gi = n0*5 + i;
            xs[i] = (gi < NN*5) ? x[gi] : 0.f;
        }
        __syncthreads();
        for (int i=tid;i<TN*64;i+=256){
            int nl=i>>6, c=i&63; int n=n0+nl;
            float a = bnode[c];
            #pragma unroll
            for (int k=0;k<5;k++) a = fmaf(xs[nl*5+k], wn[k*64+c], a);
            hs[nl*65+c] = a;
            if (n < NN) g_h[n*64+c] = a;
        }
    } else {
        int pb = (layer-1)&1;
        if (tid < 64){
            float mu = g_bnsum[pb][tid]*(1.f/NN);
            float va = g_bnsq[pb][tid]*(1.f/NN) - mu*mu;
            mus[tid] = mu;
            rss[tid] = rsqrtf(va + 1e-5f) * gamma[tid];   // fold gamma
        }
        __syncthreads();
        for (int i=tid;i<TN*64;i+=256){
            int nl=i>>6, c=i&63; int n=n0+nl;
            float hv = 0.f;
            if (n < NN){
                float g  = g_gf[n*64+c];
                float gh = (g - mus[c])*rss[c] + beta[c];
                float el = (gh > 0.f) ? gh : (__expf(gh)-1.f);
                hv = g_hf[n*64+c] + el;
                g_h[n*64+c] = hv;
            }
            hs[nl*65+c] = hv;
        }
    }
    __syncthreads();

    // main GEMM: thread = 8 nodes x 8 cols
    int oct = tid & 15, ng = tid >> 4;
    float acc[8][8];
    float bb[8];
    #pragma unroll
    for (int c=0;c<8;c++) bb[c] = bc[oct*8+c];
    #pragma unroll
    for (int j=0;j<8;j++)
        #pragma unroll
        for (int c=0;c<8;c++) acc[j][c] = bb[c];

    #pragma unroll 4
    for (int k=0;k<64;k++){
        float4 w0 = *(const float4*)&ws[k*128 + oct*8];
        float4 w1 = *(const float4*)&ws[k*128 + oct*8 + 4];
        #pragma unroll
        for (int j=0;j<8;j++){
            float hv = hs[(ng*8+j)*65 + k];
            acc[j][0] = fmaf(hv, w0.x, acc[j][0]);
            acc[j][1] = fmaf(hv, w0.y, acc[j][1]);
            acc[j][2] = fmaf(hv, w0.z, acc[j][2]);
            acc[j][3] = fmaf(hv, w0.w, acc[j][3]);
            acc[j][4] = fmaf(hv, w1.x, acc[j][4]);
            acc[j][5] = fmaf(hv, w1.y, acc[j][5]);
            acc[j][6] = fmaf(hv, w1.z, acc[j][6]);
            acc[j][7] = fmaf(hv, w1.w, acc[j][7]);
        }
    }

    #pragma unroll
    for (int j=0;j<8;j++){
        int n = n0 + ng*8 + j;
        if (n >= NN) continue;
        float4 v0 = make_float4(acc[j][0],acc[j][1],acc[j][2],acc[j][3]);
        float4 v1 = make_float4(acc[j][4],acc[j][5],acc[j][6],acc[j][7]);
        if (oct < 8){
            g_xl4[n*16 + oct*2]     = v0;
            g_xl4[n*16 + oct*2 + 1] = v1;
        } else {
            g_xr4[n*16 + (oct-8)*2]     = v0;
            g_xr4[n*16 + (oct-8)*2 + 1] = v1;
        }
    }
}

// ---------------- edge aggregation: float4, 16 threads/node ----------------
__global__ void __launch_bounds__(256) k_edge(const float* __restrict__ att,
                                              const float* __restrict__ cb,
                                              int layer)
{
    __shared__ float bsum[C], bsq[C];
    int tid = threadIdx.x;
    if (tid < C){ bsum[tid]=0.f; bsq[tid]=0.f; }
    __syncthreads();

    int n   = blockIdx.x*16 + (tid>>4);
    int l16 = tid & 15;
    unsigned gmask = 0xFu << ((tid&31) & ~3);

    float4 xr = g_xr4[n*16 + l16];
    float4 a  = ((const float4*)att)[l16];
    float4 cb4= ((const float4*)cb)[l16];

    float m = -3.0e38f, s = 0.f;
    float4 o = make_float4(0.f,0.f,0.f,0.f);
    int beg = g_rowptr[n], end = g_rowptr[n+1];
    for (int j = beg-1; j < end; j++){
        int src = (j < beg) ? n : g_col[j];
        float4 xl = g_xl4[src*16 + l16];
        float e0 = xl.x + xr.x; e0 = (e0>0.f)? e0 : 0.2f*e0;
        float e1 = xl.y + xr.y; e1 = (e1>0.f)? e1 : 0.2f*e1;
        float e2 = xl.z + xr.z; e2 = (e2>0.f)? e2 : 0.2f*e2;
        float e3 = xl.w + xr.w; e3 = (e3>0.f)? e3 : 0.2f*e3;
        float p = fmaf(e0,a.x, fmaf(e1,a.y, fmaf(e2,a.z, e3*a.w)));
        p += __shfl_xor_sync(gmask, p, 1, 4);
        p += __shfl_xor_sync(gmask, p, 2, 4);
        float nm = fmaxf(m, p);
        float sc = __expf(m - nm);
        float w  = __expf(p - nm);
        s = fmaf(s, sc, w);
        o.x = fmaf(w, xl.x, o.x*sc);
        o.y = fmaf(w, xl.y, o.y*sc);
        o.z = fmaf(w, xl.z, o.z*sc);
        o.w = fmaf(w, xl.w, o.w*sc);
        m = nm;
    }
    float inv = 1.f/s;
    float4 gv = make_float4(fmaf(o.x,inv,cb4.x), fmaf(o.y,inv,cb4.y),
                            fmaf(o.z,inv,cb4.z), fmaf(o.w,inv,cb4.w));
    g_g4[n*16 + l16] = gv;

    // BN partials: fold node-pairs via shfl(16), then shared atomics
    float q0=gv.x, q1=gv.y, q2=gv.z, q3=gv.w;
    float r0=q0*q0, r1=q1*q1, r2=q2*q2, r3=q3*q3;
    q0 += __shfl_xor_sync(0xffffffffu, q0, 16);
    q1 += __shfl_xor_sync(0xffffffffu, q1, 16);
    q2 += __shfl_xor_sync(0xffffffffu, q2, 16);
    q3 += __shfl_xor_sync(0xffffffffu, q3, 16);
    r0 += __shfl_xor_sync(0xffffffffu, r0, 16);
    r1 += __shfl_xor_sync(0xffffffffu, r1, 16);
    r2 += __shfl_xor_sync(0xffffffffu, r2, 16);
    r3 += __shfl_xor_sync(0xffffffffu, r3, 16);
    if ((tid & 31) < 16){
        atomicAdd(&bsum[l16*4+0], q0); atomicAdd(&bsum[l16*4+1], q1);
        atomicAdd(&bsum[l16*4+2], q2); atomicAdd(&bsum[l16*4+3], q3);
        atomicAdd(&bsq [l16*4+0], r0); atomicAdd(&bsq [l16*4+1], r1);
        atomicAdd(&bsq [l16*4+2], r2); atomicAdd(&bsq [l16*4+3], r3);
    }
    __syncthreads();
    if (tid < C){
        int b = layer & 1;
        atomicAdd(&g_bnsum[b][tid], bsum[tid]);
        atomicAdd(&g_bnsq [b][tid], bsq[tid]);
    }
}

// ---------------- pool with fused final update -----------------------------
__global__ void __launch_bounds__(256) k_pool(const int* __restrict__ batch, int half,
                                              const float* __restrict__ gamma,
                                              const float* __restrict__ beta)
{
    __shared__ float mus[C], rss[C];
    int tid = threadIdx.x;
    if (tid < C){
        float mu = g_bnsum[1][tid]*(1.f/NN);            // layer 7 -> buf 1
        float va = g_bnsq[1][tid]*(1.f/NN) - mu*mu;
        mus[tid] = mu;
        rss[tid] = rsqrtf(va + 1e-5f) * gamma[tid];
    }
    __syncthreads();
    const float* g_gf = (const float*)g_g4;
    int c = tid & 63, ng = tid >> 6;
    int n0 = blockIdx.x * 200;
    float acc = 0.f, cnt = 0.f;
    int cur = -1;
    for (int i=ng; i<200; i+=4){
        int n = n0 + i;
        if (n >= NN) break;
        float g  = g_gf[n*64+c];
        float gh = (g - mus[c])*rss[c] + beta[c];
        float el = (gh > 0.f) ? gh : (__expf(gh)-1.f);
        float hv = g_h[n*64+c] + el;
        int b = batch[n];
        if (b != cur){
            if (cur >= 0){
                atomicAdd(&g_pool[half*NG*C + cur*C + c], acc);
                if (c == 0) atomicAdd(&g_pcnt[half*NG + cur], cnt);
            }
            cur = b; acc = 0.f; cnt = 0.f;
        }
        acc += hv; cnt += 1.f;
    }
    if (cur >= 0){
        atomicAdd(&g_pool[half*NG*C + cur*C + c], acc);
        if (c == 0) atomicAdd(&g_pcnt[half*NG + cur], cnt);
    }
}

// ---------------- head MLP -------------------------------------------------
__global__ void __launch_bounds__(256) k_head(
        const float* __restrict__ f1w, const float* __restrict__ f1b,
        const float* __restrict__ f2w, const float* __restrict__ f2b,
        const float* __restrict__ f3w, const float* __restrict__ f3b,
        float* __restrict__ out)
{
    __shared__ float cvec[128], h1[256], h2[128];
    int b = blockIdx.x, tid = threadIdx.x;
    if (tid < 64)
        cvec[tid] = g_pool[b*C+tid] / fmaxf(g_pcnt[b], 1.f);
    else if (tid < 128)
        cvec[tid] = g_pool[NG*C + b*C + (tid-64)] / fmaxf(g_pcnt[NG+b], 1.f);
    __syncthreads();
    float a = f1b[tid];
    for (int k=0;k<128;k++) a = fmaf(cvec[k], f1w[k*256+tid], a);
    h1[tid] = fmaxf(a, 0.f);
    __syncthreads();
    if (tid < 128){
        float a2 = f2b[tid];
        for (int k=0;k<256;k++) a2 = fmaf(h1[k], f2w[k*128+tid], a2);
        h2[tid] = fmaxf(a2, 0.f);
    }
    __syncthreads();
    if (tid == 0){
        float a3 = f3b[0];
        for (int k=0;k<128;k++) a3 = fmaf(h2[k], f3w[k], a3);
        out[b] = a3;
    }
}

// ---------------- launch ----------------------------------------------------
extern "C" void kernel_launch(void* const* d_in, const int* in_sizes, int n_in,
                              void* d_out, int out_size){
    const float *x[2]; const int *ei[2]; const int *bt[2];
    if (in_sizes[1] == 2*NE){
        x[0]=(const float*)d_in[0]; ei[0]=(const int*)d_in[1]; bt[0]=(const int*)d_in[2];
        x[1]=(const float*)d_in[3]; ei[1]=(const int*)d_in[4]; bt[1]=(const int*)d_in[5];
    } else {
        x[0]=(const float*)d_in[0]; x[1]=(const float*)d_in[1];
        ei[0]=(const int*)d_in[2]; ei[1]=(const int*)d_in[3];
        bt[0]=(const int*)d_in[4]; bt[1]=(const int*)d_in[5];
    }
    const float* Wn    =(const float*)d_in[6];
    const float* bnode =(const float*)d_in[7];
    const float* Wl    =(const float*)d_in[8];
    const float* bl    =(const float*)d_in[9];
    const float* Wr    =(const float*)d_in[10];
    const float* br    =(const float*)d_in[11];
    const float* att   =(const float*)d_in[12];
    const float* cbias =(const float*)d_in[13];
    const float* gamma =(const float*)d_in[14];
    const float* beta  =(const float*)d_in[15];
    const float* f1w   =(const float*)d_in[16];
    const float* f1b   =(const float*)d_in[17];
    const float* f2w   =(const float*)d_in[18];
    const float* f2b   =(const float*)d_in[19];
    const float* f3w   =(const float*)d_in[20];
    const float* f3b   =(const float*)d_in[21];

    int gsm = (8192 + TN*65 + 128 + 64 + 64) * 4;
    cudaFuncSetAttribute(k_gemm, cudaFuncAttributeMaxDynamicSharedMemorySize, gsm);

    k_zero_pool<<<(2*NG*C+255)/256, 256>>>();
    for (int g=0; g<2; g++){
        k_zero_cnt<<<(NN+1023)/1024,1024>>>();
        k_hist   <<<NE/256,256>>>(ei[g]);
        k_scan1  <<<20,1024>>>();
        k_scan2  <<<1,32>>>();
        k_scan3  <<<20,1024>>>();
        k_scatter<<<NE/256,256>>>(ei[g]);
        for (int l=0;l<NL;l++){
            k_gemm<<<(NN+TN-1)/TN,256,gsm>>>(Wl+l*C*C, bl+l*C, Wr+l*C*C, br+l*C,
                                             gamma+l*C, beta+l*C, l,
                                             x[g], Wn, bnode);
            k_edge<<<NN/16,256>>>(att+l*C, cbias+l*C, l);
        }
        k_pool<<<NN/200,256>>>(bt[g], g, gamma+7*C, beta+7*C);
    }
    k_head<<<NG,256>>>(f1w,f1b,f2w,f2b,f3w,f3b,(float*)d_out);
}

// round 7
// speedup vs baseline: 1.4411x; 1.2023x over previous
#include <cuda_runtime.h>
#include <math.h>

#define NN 20000
#define NE 320000
#define C  64
#define NG 32
#define NL 8
#define TN 64            // gemm node tile
#define TPG 313          // tiles per graph = ceil(NN/TN)
#define EBLK 1250        // edge/hist blocks per graph (NE/256, NN/16)

// ---------------- scratch: [2] = per-graph --------------------------------
__device__ float4 g_xl4[2][NN*16];
__device__ float4 g_xr4[2][NN*16];
__device__ float4 g_g4 [2][NN*16];
__device__ float  g_h  [2][NN*C];
__device__ int    g_rowptr[2][NN+1];
__device__ int    g_cursor[2][NN];
__device__ int    g_col[2][NE];
__device__ int    g_blks[2][32];
__device__ float  g_bnsum[2][2][C];   // [graph][layer parity][C]
__device__ float  g_bnsq [2][2][C];
__device__ float  g_pool[2*NG*C];
__device__ float  g_pcnt[2*NG];

// ---------------- zero: cursors (both graphs) + pool ------------------------
__global__ void __launch_bounds__(1024) k_zero(){
    int i = blockIdx.x*1024 + threadIdx.x;
    if (i < NN)        g_cursor[0][i] = 0;
    else if (i < 2*NN) g_cursor[1][i-NN] = 0;
    if (i < 2*NG*C) g_pool[i] = 0.f;
    if (i < 2*NG)   g_pcnt[i] = 0.f;
}
__global__ void k_hist(const int* __restrict__ e0, const int* __restrict__ e1){
    int gr = blockIdx.x >= EBLK;
    const int* ei = gr ? e1 : e0;
    int e = (blockIdx.x - gr*EBLK)*256 + threadIdx.x;
    if (e < NE) atomicAdd(&g_cursor[gr][ei[NE + e]], 1);
}
__global__ void __launch_bounds__(1024) k_scan1(){
    __shared__ int s[1024];
    int gr  = blockIdx.x >= 20;
    int blk = blockIdx.x - gr*20;
    int tid = threadIdx.x;
    int gid = blk*1024 + tid;
    int v = (gid < NN) ? g_cursor[gr][gid] : 0;
    s[tid] = v; __syncthreads();
    for (int off=1; off<1024; off<<=1){
        int t = (tid>=off) ? s[tid-off] : 0;
        __syncthreads();
        s[tid] += t;
        __syncthreads();
    }
    if (gid < NN) g_rowptr[gr][gid] = s[tid] - v;   // block-local exclusive
    if (tid == 1023) g_blks[gr][blk] = s[1023];
}
__global__ void k_scan2(){
    int gr = threadIdx.x >> 5;
    if ((threadIdx.x & 31) == 0 && gr < 2){
        int r = 0;
        for (int i=0;i<20;i++){ int c = g_blks[gr][i]; g_blks[gr][i] = r; r += c; }
        g_rowptr[gr][NN] = r;
    }
}
__global__ void __launch_bounds__(1024) k_scan3(){
    int gr  = blockIdx.x >= 20;
    int blk = blockIdx.x - gr*20;
    int gid = blk*1024 + threadIdx.x;
    if (gid < NN){
        int v = g_rowptr[gr][gid] + g_blks[gr][blk];
        g_rowptr[gr][gid] = v;
        g_cursor[gr][gid] = v;
    }
}
__global__ void k_scatter(const int* __restrict__ e0, const int* __restrict__ e1){
    int gr = blockIdx.x >= EBLK;
    const int* ei = gr ? e1 : e0;
    int e = (blockIdx.x - gr*EBLK)*256 + threadIdx.x;
    if (e < NE){
        int d = ei[NE+e], s = ei[e];
        int p = atomicAdd(&g_cursor[gr][d], 1);
        g_col[gr][p] = s;
    }
}

// ---------------- fused update + dual GEMM (both graphs) --------------------
// tile < TPG -> graph 0, else graph 1. TN=64 nodes/tile, thread = 4 nodes x 8 cols.
__global__ void __launch_bounds__(256,4) k_gemm(
        const float* __restrict__ Wl, const float* __restrict__ bl,
        const float* __restrict__ Wr, const float* __restrict__ br,
        const float* __restrict__ gamma, const float* __restrict__ beta,
        int layer,
        const float* __restrict__ x0, const float* __restrict__ x1,
        const float* __restrict__ Wn, const float* __restrict__ bnode)
{
    extern __shared__ float sm[];
    float* ws  = sm;                 // 64*128
    float* hs  = sm + 8192;          // 64*65 (padded)
    float* bc  = hs + TN*65;         // 128
    float* mus = bc + 128;           // 64
    float* rss = mus + 64;           // 64
    __shared__ float wn[320];
    __shared__ float xs[TN*5];

    int tid  = threadIdx.x;
    int gr   = blockIdx.x >= TPG;
    int tloc = blockIdx.x - gr*TPG;
    int n0   = tloc * TN;
    const float* g_hf = g_h[gr];
    const float* g_gf = (const float*)g_g4[gr];

    for (int i=tid;i<8192;i+=256){
        int k=i>>7, c=i&127;
        ws[i] = (c<64) ? Wl[k*64+c] : Wr[k*64+(c-64)];
    }
    if (tid < 128) bc[tid] = (tid<64) ? bl[tid] : br[tid-64];
    if (tloc == 0 && tid >= 128 && tid < 256){   // zero this graph+layer BN buffer
        int nb = layer & 1, t = tid - 128;
        if (t < 64) g_bnsum[gr][nb][t] = 0.f; else g_bnsq[gr][nb][t-64] = 0.f;
    }

    if (layer == 0){
        const float* x = gr ? x1 : x0;
        for (int i=tid;i<320;i+=256) wn[i] = Wn[i];
        for (int i=tid;i<TN*5;i+=256){
            int gi = n0*5 + i;
            xs[i] = (gi < NN*5) ? x[gi] : 0.f;
        }
        __syncthreads();
        for (int i=tid;i<TN*64;i+=256){
            int nl=i>>6, c=i&63; int n=n0+nl;
            float a = bnode[c];
            #pragma unroll
            for (int k=0;k<5;k++) a = fmaf(xs[nl*5+k], wn[k*64+c], a);
            hs[nl*65+c] = a;
            if (n < NN) g_h[gr][n*64+c] = a;
        }
    } else {
        int pb = (layer-1)&1;
        if (tid < 64){
            float mu = g_bnsum[gr][pb][tid]*(1.f/NN);
            float va = g_bnsq[gr][pb][tid]*(1.f/NN) - mu*mu;
            mus[tid] = mu;
            rss[tid] = rsqrtf(va + 1e-5f) * gamma[tid];   // fold gamma
        }
        __syncthreads();
        for (int i=tid;i<TN*64;i+=256){
            int nl=i>>6, c=i&63; int n=n0+nl;
            float hv = 0.f;
            if (n < NN){
                float g  = g_gf[n*64+c];
                float gh = (g - mus[c])*rss[c] + beta[c];
                float el = (gh > 0.f) ? gh : (__expf(gh)-1.f);
                hv = g_hf[n*64+c] + el;
                g_h[gr][n*64+c] = hv;
            }
            hs[nl*65+c] = hv;
        }
    }
    __syncthreads();

    // main GEMM: thread = 4 nodes x 8 cols
    int oct = tid & 15, ng = tid >> 4;    // 16 groups x 4 nodes
    float acc[4][8];
    #pragma unroll
    for (int j=0;j<4;j++)
        #pragma unroll
        for (int c=0;c<8;c++) acc[j][c] = bc[oct*8+c];

    #pragma unroll 4
    for (int k=0;k<64;k++){
        float4 w0 = *(const float4*)&ws[k*128 + oct*8];
        float4 w1 = *(const float4*)&ws[k*128 + oct*8 + 4];
        #pragma unroll
        for (int j=0;j<4;j++){
            float hv = hs[(ng*4+j)*65 + k];
            acc[j][0] = fmaf(hv, w0.x, acc[j][0]);
            acc[j][1] = fmaf(hv, w0.y, acc[j][1]);
            acc[j][2] = fmaf(hv, w0.z, acc[j][2]);
            acc[j][3] = fmaf(hv, w0.w, acc[j][3]);
            acc[j][4] = fmaf(hv, w1.x, acc[j][4]);
            acc[j][5] = fmaf(hv, w1.y, acc[j][5]);
            acc[j][6] = fmaf(hv, w1.z, acc[j][6]);
            acc[j][7] = fmaf(hv, w1.w, acc[j][7]);
        }
    }

    #pragma unroll
    for (int j=0;j<4;j++){
        int n = n0 + ng*4 + j;
        if (n >= NN) continue;
        float4 v0 = make_float4(acc[j][0],acc[j][1],acc[j][2],acc[j][3]);
        float4 v1 = make_float4(acc[j][4],acc[j][5],acc[j][6],acc[j][7]);
        if (oct < 8){
            g_xl4[gr][n*16 + oct*2]     = v0;
            g_xl4[gr][n*16 + oct*2 + 1] = v1;
        } else {
            g_xr4[gr][n*16 + (oct-8)*2]     = v0;
            g_xr4[gr][n*16 + (oct-8)*2 + 1] = v1;
        }
    }
}

// ---------------- edge aggregation: float4, 16 threads/node, both graphs ----
__global__ void __launch_bounds__(256) k_edge(const float* __restrict__ att,
                                              const float* __restrict__ cb,
                                              int layer)
{
    __shared__ float bsum[C], bsq[C];
    int tid = threadIdx.x;
    if (tid < C){ bsum[tid]=0.f; bsq[tid]=0.f; }
    __syncthreads();

    int gr  = blockIdx.x >= EBLK;
    int blk = blockIdx.x - gr*EBLK;
    int n   = blk*16 + (tid>>4);
    int l16 = tid & 15;
    unsigned gmask = 0xFu << ((tid&31) & ~3);
    const float4* xl4 = g_xl4[gr];

    float4 xr = g_xr4[gr][n*16 + l16];
    float4 a  = ((const float4*)att)[l16];
    float4 cb4= ((const float4*)cb)[l16];

    float m = -3.0e38f, s = 0.f;
    float4 o = make_float4(0.f,0.f,0.f,0.f);
    int beg = g_rowptr[gr][n], end = g_rowptr[gr][n+1];
    const int* col = g_col[gr];
    for (int j = beg-1; j < end; j++){
        int src = (j < beg) ? n : col[j];
        float4 xl = xl4[src*16 + l16];
        float e0 = xl.x + xr.x; e0 = (e0>0.f)? e0 : 0.2f*e0;
        float e1 = xl.y + xr.y; e1 = (e1>0.f)? e1 : 0.2f*e1;
        float e2 = xl.z + xr.z; e2 = (e2>0.f)? e2 : 0.2f*e2;
        float e3 = xl.w + xr.w; e3 = (e3>0.f)? e3 : 0.2f*e3;
        float p = fmaf(e0,a.x, fmaf(e1,a.y, fmaf(e2,a.z, e3*a.w)));
        p += __shfl_xor_sync(gmask, p, 1, 4);
        p += __shfl_xor_sync(gmask, p, 2, 4);
        float nm = fmaxf(m, p);
        float sc = __expf(m - nm);
        float w  = __expf(p - nm);
        s = fmaf(s, sc, w);
        o.x = fmaf(w, xl.x, o.x*sc);
        o.y = fmaf(w, xl.y, o.y*sc);
        o.z = fmaf(w, xl.z, o.z*sc);
        o.w = fmaf(w, xl.w, o.w*sc);
        m = nm;
    }
    float inv = 1.f/s;
    float4 gv = make_float4(fmaf(o.x,inv,cb4.x), fmaf(o.y,inv,cb4.y),
                            fmaf(o.z,inv,cb4.z), fmaf(o.w,inv,cb4.w));
    g_g4[gr][n*16 + l16] = gv;

    float q0=gv.x, q1=gv.y, q2=gv.z, q3=gv.w;
    float r0=q0*q0, r1=q1*q1, r2=q2*q2, r3=q3*q3;
    q0 += __shfl_xor_sync(0xffffffffu, q0, 16);
    q1 += __shfl_xor_sync(0xffffffffu, q1, 16);
    q2 += __shfl_xor_sync(0xffffffffu, q2, 16);
    q3 += __shfl_xor_sync(0xffffffffu, q3, 16);
    r0 += __shfl_xor_sync(0xffffffffu, r0, 16);
    r1 += __shfl_xor_sync(0xffffffffu, r1, 16);
    r2 += __shfl_xor_sync(0xffffffffu, r2, 16);
    r3 += __shfl_xor_sync(0xffffffffu, r3, 16);
    if ((tid & 31) < 16){
        atomicAdd(&bsum[l16*4+0], q0); atomicAdd(&bsum[l16*4+1], q1);
        atomicAdd(&bsum[l16*4+2], q2); atomicAdd(&bsum[l16*4+3], q3);
        atomicAdd(&bsq [l16*4+0], r0); atomicAdd(&bsq [l16*4+1], r1);
        atomicAdd(&bsq [l16*4+2], r2); atomicAdd(&bsq [l16*4+3], r3);
    }
    __syncthreads();
    if (tid < C){
        int b = layer & 1;
        atomicAdd(&g_bnsum[gr][b][tid], bsum[tid]);
        atomicAdd(&g_bnsq [gr][b][tid], bsq[tid]);
    }
}

// ---------------- pool with fused final update (both graphs) ----------------
__global__ void __launch_bounds__(256) k_pool(const int* __restrict__ b0,
                                              const int* __restrict__ b1,
                                              const float* __restrict__ gamma,
                                              const float* __restrict__ beta)
{
    __shared__ float mus[C], rss[C];
    int gr = blockIdx.x >= 100;
    int blk = blockIdx.x - gr*100;
    const int* batch = gr ? b1 : b0;
    int tid = threadIdx.x;
    if (tid < C){
        float mu = g_bnsum[gr][1][tid]*(1.f/NN);        // layer 7 -> parity 1
        float va = g_bnsq[gr][1][tid]*(1.f/NN) - mu*mu;
        mus[tid] = mu;
        rss[tid] = rsqrtf(va + 1e-5f) * gamma[tid];
    }
    __syncthreads();
    const float* g_gf = (const float*)g_g4[gr];
    const float* g_hf = g_h[gr];
    int c = tid & 63, ng = tid >> 6;
    int n0 = blk * 200;
    float acc = 0.f, cnt = 0.f;
    int cur = -1;
    for (int i=ng; i<200; i+=4){
        int n = n0 + i;
        if (n >= NN) break;
        float g  = g_gf[n*64+c];
        float gh = (g - mus[c])*rss[c] + beta[c];
        float el = (gh > 0.f) ? gh : (__expf(gh)-1.f);
        float hv = g_hf[n*64+c] + el;
        int b = batch[n];
        if (b != cur){
            if (cur >= 0){
                atomicAdd(&g_pool[gr*NG*C + cur*C + c], acc);
                if (c == 0) atomicAdd(&g_pcnt[gr*NG + cur], cnt);
            }
            cur = b; acc = 0.f; cnt = 0.f;
        }
        acc += hv; cnt += 1.f;
    }
    if (cur >= 0){
        atomicAdd(&g_pool[gr*NG*C + cur*C + c], acc);
        if (c == 0) atomicAdd(&g_pcnt[gr*NG + cur], cnt);
    }
}

// ---------------- head MLP -------------------------------------------------
__global__ void __launch_bounds__(256) k_head(
        const float* __restrict__ f1w, const float* __restrict__ f1b,
        const float* __restrict__ f2w, const float* __restrict__ f2b,
        const float* __restrict__ f3w, const float* __restrict__ f3b,
        float* __restrict__ out)
{
    __shared__ float cvec[128], h1[256], h2[128];
    int b = blockIdx.x, tid = threadIdx.x;
    if (tid < 64)
        cvec[tid] = g_pool[b*C+tid] / fmaxf(g_pcnt[b], 1.f);
    else if (tid < 128)
        cvec[tid] = g_pool[NG*C + b*C + (tid-64)] / fmaxf(g_pcnt[NG+b], 1.f);
    __syncthreads();
    float a = f1b[tid];
    for (int k=0;k<128;k++) a = fmaf(cvec[k], f1w[k*256+tid], a);
    h1[tid] = fmaxf(a, 0.f);
    __syncthreads();
    if (tid < 128){
        float a2 = f2b[tid];
        for (int k=0;k<256;k++) a2 = fmaf(h1[k], f2w[k*128+tid], a2);
        h2[tid] = fmaxf(a2, 0.f);
    }
    __syncthreads();
    if (tid == 0){
        float a3 = f3b[0];
        for (int k=0;k<128;k++) a3 = fmaf(h2[k], f3w[k], a3);
        out[b] = a3;
    }
}

// ---------------- launch ----------------------------------------------------
extern "C" void kernel_launch(void* const* d_in, const int* in_sizes, int n_in,
                              void* d_out, int out_size){
    const float *x[2]; const int *ei[2]; const int *bt[2];
    if (in_sizes[1] == 2*NE){
        x[0]=(const float*)d_in[0]; ei[0]=(const int*)d_in[1]; bt[0]=(const int*)d_in[2];
        x[1]=(const float*)d_in[3]; ei[1]=(const int*)d_in[4]; bt[1]=(const int*)d_in[5];
    } else {
        x[0]=(const float*)d_in[0]; x[1]=(const float*)d_in[1];
        ei[0]=(const int*)d_in[2]; ei[1]=(const int*)d_in[3];
        bt[0]=(const int*)d_in[4]; bt[1]=(const int*)d_in[5];
    }
    const float* Wn    =(const float*)d_in[6];
    const float* bnode =(const float*)d_in[7];
    const float* Wl    =(const float*)d_in[8];
    const float* bl    =(const float*)d_in[9];
    const float* Wr    =(const float*)d_in[10];
    const float* br    =(const float*)d_in[11];
    const float* att   =(const float*)d_in[12];
    const float* cbias =(const float*)d_in[13];
    const float* gamma =(const float*)d_in[14];
    const float* beta  =(const float*)d_in[15];
    const float* f1w   =(const float*)d_in[16];
    const float* f1b   =(const float*)d_in[17];
    const float* f2w   =(const float*)d_in[18];
    const float* f2b   =(const float*)d_in[19];
    const float* f3w   =(const float*)d_in[20];
    const float* f3b   =(const float*)d_in[21];

    int gsm = (8192 + TN*65 + 128 + 64 + 64) * 4;
    cudaFuncSetAttribute(k_gemm, cudaFuncAttributeMaxDynamicSharedMemorySize, gsm);

    k_zero   <<<(2*NN+1023)/1024,1024>>>();
    k_hist   <<<2*EBLK,256>>>(ei[0], ei[1]);
    k_scan1  <<<40,1024>>>();
    k_scan2  <<<1,64>>>();
    k_scan3  <<<40,1024>>>();
    k_scatter<<<2*EBLK,256>>>(ei[0], ei[1]);
    for (int l=0;l<NL;l++){
        k_gemm<<<2*TPG,256,gsm>>>(Wl+l*C*C, bl+l*C, Wr+l*C*C, br+l*C,
                                  gamma+l*C, beta+l*C, l,
                                  x[0], x[1], Wn, bnode);
        k_edge<<<2*EBLK,256>>>(att+l*C, cbias+l*C, l);
    }
    k_pool<<<200,256>>>(bt[0], bt[1], gamma+7*C, beta+7*C);
    k_head<<<NG,256>>>(f1w,f1b,f2w,f2b,f3w,f3b,(float*)d_out);
}